// round 6
// baseline (speedup 1.0000x reference)
#include <cuda_runtime.h>

// ---------------------------------------------------------------------------
// EResidualBlockBucket: x -> grouped3x3+ReLU -> per-pixel bucket-indexed
// dynamic 3x3 conv (+per-pixel bias) -> ReLU -> 1x1 conv -> +x -> ReLU
//
// R5: k_dyn measured ~4x above its FMA/issue floor -> latency/barrier bound
// (only 12 warps/SM). This round: (a) k_zero deleted (g_hpad border stays
// zero from static zero-init; k_gconv rewrites the interior every call),
// (b) k_dyn at 512 threads / 16 warps (4 ocs per warp) for 2x latency
// hiding, (c) f32x2 packed FMA on oc-pairs (fma.rn.f32x2, Blackwell dual
// fp32) with pair-interleaved weight staging -> half the FMA instructions.
// ---------------------------------------------------------------------------

#define HPW 66                 // padded image width/height
#define HPSZ (64 * HPW * HPW)  // h_pad elements: [y][x][ic], ic fastest

// Zero-initialized at module load; k_gconv overwrites the interior each call,
// the 1-px halo border is never written -> stays zero (SAME padding).
__device__ __align__(16) float g_hpad[HPSZ];     // padded h, pixel-major

typedef unsigned long long ull;

__device__ __forceinline__ void ffma2(ull& d, ull a, ull b) {
    asm("fma.rn.f32x2 %0, %1, %2, %0;" : "+l"(d) : "l"(a), "l"(b));
}
__device__ __forceinline__ ull pack2(float v) {
    ull r; asm("mov.b64 %0, {%1, %1};" : "=l"(r) : "f"(v)); return r;
}
__device__ __forceinline__ ull packf(float lo, float hi) {
    ull r; asm("mov.b64 %0, {%1, %2};" : "=l"(r) : "f"(lo), "f"(hi)); return r;
}
__device__ __forceinline__ float2 unpack2(ull v) {
    float2 r; asm("mov.b64 {%0, %1}, %2;" : "=f"(r.x), "=f"(r.y) : "l"(v));
    return r;
}

// ---------------- K1: grouped 3x3 conv + bias + ReLU -> g_hpad -------------
// grid: 64 blocks = 4 groups x 16 tiles (16x16 px). 256 threads.
__global__ void __launch_bounds__(256) k_gconv(const float* __restrict__ x,
                                               const float* __restrict__ w1,
                                               const float* __restrict__ b1) {
    __shared__ float xs[16][18][18];   // input tile + halo, one group (16 ic)
    __shared__ float ws[16][144];      // weights for 16 oc of this group
    __shared__ float bs[16];

    int bx = blockIdx.x;
    int g = bx >> 4;                   // group 0..3
    int tile = bx & 15;
    int y0 = (tile >> 2) * 16, x0 = (tile & 3) * 16;
    int tid = threadIdx.x;

    for (int i = tid; i < 16 * 18 * 18; i += 256) {
        int ic = i / 324;
        int rem = i - ic * 324;
        int r = rem / 18, c = rem - r * 18;
        int yy = y0 - 1 + r, xx = x0 - 1 + c;
        float v = 0.f;
        if (yy >= 0 && yy < 64 && xx >= 0 && xx < 64)
            v = x[(g * 16 + ic) * 4096 + yy * 64 + xx];
        xs[ic][r][c] = v;
    }
    for (int i = tid; i < 16 * 144; i += 256) {
        int oc = i / 144;
        ws[oc][i - oc * 144] = w1[(g * 16 + oc) * 144 + (i - oc * 144)];
    }
    if (tid < 16) bs[tid] = b1[g * 16 + tid];
    __syncthreads();

    int r = tid >> 4, c = tid & 15;
    float acc[16];
#pragma unroll
    for (int j = 0; j < 16; ++j) acc[j] = bs[j];

    for (int ic = 0; ic < 16; ++ic) {
        float p[9];
#pragma unroll
        for (int dy = 0; dy < 3; ++dy)
#pragma unroll
            for (int dx = 0; dx < 3; ++dx)
                p[dy * 3 + dx] = xs[ic][r + dy][c + dx];
#pragma unroll
        for (int j = 0; j < 16; ++j) {
#pragma unroll
            for (int k = 0; k < 9; ++k)
                acc[j] = fmaf(ws[j][ic * 9 + k], p[k], acc[j]);
        }
    }
    // write pixel-major padded layout: h_pad[((y+1)*66 + (x+1))*64 + oc]
    float* dst = g_hpad + (((y0 + r + 1) * HPW) + (x0 + c + 1)) * 64 + g * 16;
#pragma unroll
    for (int j = 0; j < 16; ++j) dst[j] = fmaxf(acc[j], 0.f);
}

// ---------------- K2: bucket-grouped dynamic conv + fused epilogue ---------
// grid: 216 blocks (one per type), 512 threads = 16 warps; warp w owns
// ocs [4w, 4w+4) = oc-pairs {2w, 2w+1}; lanes = pixel slots (chunks of 32).
__global__ void __launch_bounds__(512) k_dyn(const int* __restrict__ buckets,
                                             const float* __restrict__ emb,
                                             const float* __restrict__ x,
                                             const float* __restrict__ w2,
                                             const float* __restrict__ b2,
                                             float* __restrict__ out) {
    // ws: pair-interleaved weights ws[pair*144 + c*2 + parity] so one
    // LDS.128 (ulonglong2) yields f32x2 operands for 2 consecutive c.
    __shared__ __align__(16) float ws[64 * 72];  // 18.4 KB
    __shared__ __align__(16) float ps[72 * 33];  // patches [c_local][slot]
    __shared__ unsigned short plist[4096];
    __shared__ int s_count;
    float* ds = ps;   // epilogue overlay (64x33 = 2112 <= 2376 floats)

    int t = blockIdx.x;
    int tid = threadIdx.x;
    if (tid == 0) s_count = 0;
    __syncthreads();
    for (int i = tid; i < 4096; i += 512) {
        if (buckets[i] == t) {
            int p = atomicAdd(&s_count, 1);
            plist[p] = (unsigned short)i;
        }
    }
    __syncthreads();
    int n = s_count;
    if (n == 0) return;

    int lane = tid & 31;
    int wid = tid >> 5;               // 0..15
    int oc_base = wid * 4;
    const float* W = emb + (size_t)t * 36928;

    for (int chunk = 0; chunk < n; chunk += 32) {
        int pi = chunk + lane;
        int mypix = plist[pi < n ? pi : n - 1];

        // packed accumulators: acc2[0]=(oc0,oc1), acc2[1]=(oc2,oc3)
        ull acc2[2];
        acc2[0] = packf(__ldg(W + (oc_base + 0) * 577 + 576),
                        __ldg(W + (oc_base + 1) * 577 + 576));
        acc2[1] = packf(__ldg(W + (oc_base + 2) * 577 + 576),
                        __ldg(W + (oc_base + 3) * 577 + 576));

        for (int icc8 = 0; icc8 < 8; ++icc8) {
            int icc = icc8 * 8;  // ic chunk [icc, icc+8)

            // ---- stage patches: 32 px x 9 positions x 8 ic = 576 float4s
            for (int t2 = tid; t2 < 576; t2 += 512) {
                int q = t2 & 1;
                int r = t2 >> 1;          // 0..287
                int slot = r / 9;
                int pos = r - slot * 9;   // dy*3+dx
                int pj = chunk + slot;
                int pix = plist[pj < n ? pj : n - 1];
                int y = pix >> 6, xx = pix & 63;
                int dy = pos / 3, dx = pos - dy * 3;
                const float4 v = *(const float4*)(g_hpad +
                    (((y + dy) * HPW) + (xx + dx)) * 64 + icc + q * 4);
                int base_ic = q * 4;
                ps[((base_ic + 0) * 9 + pos) * 33 + slot] = v.x;
                ps[((base_ic + 1) * 9 + pos) * 33 + slot] = v.y;
                ps[((base_ic + 2) * 9 + pos) * 33 + slot] = v.z;
                ps[((base_ic + 3) * 9 + pos) * 33 + slot] = v.w;
            }
            // ---- stage weights pair-interleaved: 64 oc x 72 c
            {
                const float* Wc = W + icc * 9;
                for (int i2 = tid; i2 < 4608; i2 += 512) {
                    int oc = i2 / 72;
                    int cl = i2 - oc * 72;
                    ws[(oc >> 1) * 144 + cl * 2 + (oc & 1)] =
                        __ldg(Wc + oc * 577 + cl);
                }
            }
            __syncthreads();

            // ---- compute: 72 c x 2 oc-pairs per warp, FFMA2
            const float* psl = ps + lane;
            const ulonglong2* wp0 =
                ((const ulonglong2*)ws) + (2 * wid) * 36;
            const ulonglong2* wp1 = wp0 + 36;
#pragma unroll 6
            for (int c4 = 0; c4 < 72; c4 += 4) {
                ull p0 = pack2(psl[(c4 + 0) * 33]);
                ull p1 = pack2(psl[(c4 + 1) * 33]);
                ull p2 = pack2(psl[(c4 + 2) * 33]);
                ull p3 = pack2(psl[(c4 + 3) * 33]);
                ulonglong2 a01 = wp0[(c4 >> 1)];
                ulonglong2 a23 = wp0[(c4 >> 1) + 1];
                ulonglong2 b01 = wp1[(c4 >> 1)];
                ulonglong2 b23 = wp1[(c4 >> 1) + 1];
                ffma2(acc2[0], a01.x, p0);
                ffma2(acc2[0], a01.y, p1);
                ffma2(acc2[0], a23.x, p2);
                ffma2(acc2[0], a23.y, p3);
                ffma2(acc2[1], b01.x, p0);
                ffma2(acc2[1], b01.y, p1);
                ffma2(acc2[1], b23.x, p2);
                ffma2(acc2[1], b23.y, p3);
            }
            __syncthreads();   // protects ps/ws before restage / ds overlay
        }

        // ---- fused epilogue: ReLU -> 1x1 conv (w2) + b2 -> +x -> ReLU
        float2 r01 = unpack2(acc2[0]);
        float2 r23 = unpack2(acc2[1]);
        ds[(oc_base + 0) * 33 + lane] = fmaxf(r01.x, 0.f);
        ds[(oc_base + 1) * 33 + lane] = fmaxf(r01.y, 0.f);
        ds[(oc_base + 2) * 33 + lane] = fmaxf(r23.x, 0.f);
        ds[(oc_base + 3) * 33 + lane] = fmaxf(r23.y, 0.f);
        __syncthreads();

        float eacc[4];
#pragma unroll
        for (int j = 0; j < 4; ++j) eacc[j] = __ldg(b2 + oc_base + j);

#pragma unroll
        for (int blk = 0; blk < 4; ++blk) {      // 16 ic at a time
            float pv[16];
#pragma unroll
            for (int q = 0; q < 16; ++q)
                pv[q] = ds[(blk * 16 + q) * 33 + lane];
#pragma unroll
            for (int j = 0; j < 4; ++j) {
                const float4* wr = (const float4*)(w2 +
                    (oc_base + j) * 64 + blk * 16);  // uniform, L1-resident
#pragma unroll
                for (int q4 = 0; q4 < 4; ++q4) {
                    float4 w = __ldg(wr + q4);
                    eacc[j] = fmaf(w.x, pv[q4 * 4 + 0], eacc[j]);
                    eacc[j] = fmaf(w.y, pv[q4 * 4 + 1], eacc[j]);
                    eacc[j] = fmaf(w.z, pv[q4 * 4 + 2], eacc[j]);
                    eacc[j] = fmaf(w.w, pv[q4 * 4 + 3], eacc[j]);
                }
            }
        }

        if (pi < n) {
#pragma unroll
            for (int j = 0; j < 4; ++j) {
                int o = oc_base + j;
                out[o * 4096 + mypix] =
                    fmaxf(eacc[j] + __ldg(x + o * 4096 + mypix), 0.f);
            }
        }
        __syncthreads();   // ds (== ps) must drain before next chunk restages
    }
}

// ---------------------------------------------------------------------------
extern "C" void kernel_launch(void* const* d_in, const int* in_sizes, int n_in,
                              void* d_out, int out_size) {
    const float* x       = (const float*)d_in[0];
    const int*   buckets = (const int*)  d_in[1];
    const float* w1      = (const float*)d_in[2];
    const float* b1      = (const float*)d_in[3];
    const float* emb     = (const float*)d_in[4];
    const float* w2      = (const float*)d_in[5];
    const float* b2      = (const float*)d_in[6];
    float* out = (float*)d_out;

    k_gconv<<<64, 256>>>(x, w1, b1);
    k_dyn<<<216, 512>>>(buckets, emb, x, w2, b2, out);
}